// round 3
// baseline (speedup 1.0000x reference)
#include <cuda_runtime.h>
#include <cuda_fp16.h>
#include <cstdint>
#include <cstddef>

// ---------------------------------------------------------------------------
// Problem constants
// ---------------------------------------------------------------------------
#define MDIM 4096
#define KDIM 4096
#define NDIM 12288
// GROUP = 64

// GEMM tiling
#define TM 128
#define TN 256
#define TKC 64
#define STAGES 3
#define KITERS (KDIM / TKC)           // 64
#define TILES_M (MDIM / TM)           // 32
#define TILES_N (NDIM / TN)           // 48
#define STAGE_BYTES 65536             // Ah 16K + Al 16K + B 32K
#define NTHREADS 512
// layout: [align slack 1024][meta 1024][stages 3*64K]
#define SMEM_TOTAL (1024 + 1024 + STAGES * STAGE_BYTES)

// ---------------------------------------------------------------------------
// Scratch (device globals: no allocation allowed)
// ---------------------------------------------------------------------------
__device__ __half g_Xh[(size_t)MDIM * KDIM];   // 32 MB
__device__ __half g_Xl[(size_t)MDIM * KDIM];   // 32 MB
__device__ __half g_Wt[(size_t)NDIM * KDIM];   // 96 MB  W^T [N, K], K contiguous

// ---------------------------------------------------------------------------
// Prepass 1: exact fp16 hi/lo split of X
// ---------------------------------------------------------------------------
__global__ void __launch_bounds__(256) split_x_kernel(const float4* __restrict__ x) {
    int i = blockIdx.x * blockDim.x + threadIdx.x;
    float4 v = x[i];
    __half2 h0 = __floats2half2_rn(v.x, v.y);
    __half2 h1 = __floats2half2_rn(v.z, v.w);
    float2 f0 = __half22float2(h0);
    float2 f1 = __half22float2(h1);
    __half2 l0 = __floats2half2_rn(v.x - f0.x, v.y - f0.y);
    __half2 l1 = __floats2half2_rn(v.z - f1.x, v.w - f1.y);
    __half2* xh = reinterpret_cast<__half2*>(g_Xh);
    __half2* xl = reinterpret_cast<__half2*>(g_Xl);
    xh[2 * i]     = h0;
    xh[2 * i + 1] = h1;
    xl[2 * i]     = l0;
    xl[2 * i + 1] = l1;
}

// ---------------------------------------------------------------------------
// Prepass 2: dequant q[K,N] (codes 0..3) -> fp16 W^T [N,K] via SMEM transpose
// ---------------------------------------------------------------------------
__global__ void __launch_bounds__(256) dequant_kernel(const int* __restrict__ q,
                                                      const float* __restrict__ scale,
                                                      const float* __restrict__ zp) {
    __shared__ __half tile[32][34];
    const int n0 = blockIdx.x * 32;
    const int k0 = blockIdx.y * 32;   // 32 | 64 -> single group per k-tile
    const int tx = threadIdx.x;       // 0..31
    const int ty = threadIdx.y;       // 0..7
    const int g = k0 >> 6;
    const float s = scale[(size_t)g * NDIM + n0 + tx];
    const float z = zp[(size_t)g * NDIM + n0 + tx];
#pragma unroll
    for (int r = 0; r < 4; ++r) {
        int k = k0 + ty + r * 8;
        int qq = q[(size_t)k * NDIM + n0 + tx];
        tile[ty + r * 8][tx] = __float2half((float)qq * s + z);
    }
    __syncthreads();
#pragma unroll
    for (int r = 0; r < 4; ++r) {
        int n = n0 + ty + r * 8;
        g_Wt[(size_t)n * KDIM + k0 + tx] = tile[tx][ty + r * 8];
    }
}

// ---------------------------------------------------------------------------
// Common PTX helpers (compute_103-safe)
// ---------------------------------------------------------------------------
__device__ __forceinline__ uint32_t smem_u32(const void* p) {
    uint32_t a;
    asm("{ .reg .u64 t; cvta.to.shared.u64 t, %1; cvt.u32.u64 %0, t; }" : "=r"(a) : "l"(p));
    return a;
}

__device__ __forceinline__ void cp_async16(uint32_t dst, const void* src) {
    asm volatile("cp.async.cg.shared.global [%0], [%1], 16;" :: "r"(dst), "l"(src) : "memory");
}

__device__ __forceinline__ void cp_commit() {
    asm volatile("cp.async.commit_group;" ::: "memory");
}

__device__ __forceinline__ void cp_wait2() {
    asm volatile("cp.async.wait_group 2;" ::: "memory");
}

// Stage fill: Ah/Al (128x64 fp16) + B (256x64 fp16), 128B rows, XOR swizzle
__device__ __forceinline__ void fill_stage(int kc, uint32_t stage_sm, int m0, int n0, int tid) {
    const size_t koff = (size_t)kc * TKC;
    const char* xh = (const char*)g_Xh;
    const char* xl = (const char*)g_Xl;
    const char* wt = (const char*)g_Wt;
#pragma unroll
    for (int c = tid; c < 1024; c += NTHREADS) {      // A planes: 1024 chunks of 16B
        int row = c >> 3;
        uint32_t off = (uint32_t)c * 16;
        uint32_t sw = off ^ ((off >> 3) & 0x70);
        size_t gb = (((size_t)(m0 + row)) * KDIM + koff) * 2 + (size_t)(c & 7) * 16;
        cp_async16(stage_sm + sw, xh + gb);
        cp_async16(stage_sm + 16384 + sw, xl + gb);
    }
#pragma unroll
    for (int c = tid; c < 2048; c += NTHREADS) {      // B: 2048 chunks of 16B
        int row = c >> 3;
        uint32_t off = (uint32_t)c * 16;
        uint32_t sw = off ^ ((off >> 3) & 0x70);
        size_t gb = (((size_t)(n0 + row)) * KDIM + koff) * 2 + (size_t)(c & 7) * 16;
        cp_async16(stage_sm + 32768 + sw, wt + gb);
    }
}

#if defined(__CUDA_ARCH__) && defined(__CUDA_ARCH_FEAT_SM103_ALL)
// ===========================================================================
// tcgen05 path (only if the PTX target is sm_103a)
// ===========================================================================
__device__ __forceinline__ void mbar_init(uint32_t a, uint32_t cnt) {
    asm volatile("mbarrier.init.shared.b64 [%0], %1;" :: "r"(a), "r"(cnt) : "memory");
}
__device__ __forceinline__ void mbar_wait(uint32_t a, uint32_t parity) {
    asm volatile(
        "{\n\t.reg .pred P;\n\t"
        "W%=:\n\t"
        "mbarrier.try_wait.parity.acquire.cta.shared::cta.b64 P, [%0], %1, 0x989680;\n\t"
        "@P bra D%=;\n\t"
        "bra W%=;\n\t"
        "D%=:\n\t}"
        :: "r"(a), "r"(parity) : "memory");
}
__device__ __forceinline__ void cp_async_arrive(uint32_t bar) {
    asm volatile("cp.async.mbarrier.arrive.noinc.shared::cta.b64 [%0];" :: "r"(bar) : "memory");
}
__device__ __forceinline__ void fence_proxy_async_shared() {
    asm volatile("fence.proxy.async.shared::cta;" ::: "memory");
}
__device__ __forceinline__ uint64_t make_desc(uint32_t smem_addr) {
    const uint64_t base = (uint64_t(2) << 61) | (uint64_t(1) << 46) |
                          (uint64_t(64) << 32) | (uint64_t(1) << 16);
    return base | ((uint64_t)(smem_addr >> 4) & 0x3FFF);
}
#define MMA_IDESC ((1u << 4) | ((128u / 8) << 17) | ((128u / 16) << 24))
__device__ __forceinline__ void mma_f16_ss(uint32_t d_tmem, uint64_t a_desc,
                                           uint64_t b_desc, uint32_t acc) {
    asm volatile(
        "{\n\t.reg .pred p;\n\t"
        "setp.ne.u32 p, %4, 0;\n\t"
        "tcgen05.mma.cta_group::1.kind::f16 [%0], %1, %2, %3, {%5, %5, %5, %5}, p;\n\t"
        "}"
        :: "r"(d_tmem), "l"(a_desc), "l"(b_desc), "r"(MMA_IDESC), "r"(acc), "r"(0u)
        : "memory");
}
__device__ __forceinline__ void tcgen05_commit(uint32_t bar) {
    asm volatile(
        "tcgen05.commit.cta_group::1.mbarrier::arrive::one.shared::cluster.b64 [%0];"
        :: "r"(bar) : "memory");
}
#define TCGEN05_ALLOC(a, n)                                                        \
    asm volatile("tcgen05.alloc.cta_group::1.sync.aligned.shared::cta.b32 [%0], %1;" \
                 :: "r"((uint32_t)(a)), "r"((uint32_t)(n)) : "memory")
#define TCGEN05_DEALLOC(t, n)                                                      \
    asm volatile("tcgen05.dealloc.cta_group::1.sync.aligned.b32 %0, %1;"           \
                 :: "r"(t), "r"((uint32_t)(n)))
#define TCGEN05_RELINQUISH()                                                       \
    asm volatile("tcgen05.relinquish_alloc_permit.cta_group::1.sync.aligned;")
#define TCGEN05_WAIT_LD() asm volatile("tcgen05.wait::ld.sync.aligned;" ::: "memory")
#define TCGEN05_FENCE_BEFORE() asm volatile("tcgen05.fence::before_thread_sync;" ::: "memory")
#define TCGEN05_FENCE_AFTER()  asm volatile("tcgen05.fence::after_thread_sync;" ::: "memory")
#define TCGEN05_LD_32X32B_X32(r, tmem_addr) \
    asm volatile( \
        "tcgen05.ld.sync.aligned.32x32b.x32.b32 " \
        "{%0, %1, %2, %3, %4, %5, %6, %7, " \
        " %8, %9, %10, %11, %12, %13, %14, %15, " \
        " %16, %17, %18, %19, %20, %21, %22, %23, " \
        " %24, %25, %26, %27, %28, %29, %30, %31}, [%32];" \
        : "=r"((r)[0]),  "=r"((r)[1]),  "=r"((r)[2]),  "=r"((r)[3]), \
          "=r"((r)[4]),  "=r"((r)[5]),  "=r"((r)[6]),  "=r"((r)[7]), \
          "=r"((r)[8]),  "=r"((r)[9]),  "=r"((r)[10]), "=r"((r)[11]), \
          "=r"((r)[12]), "=r"((r)[13]), "=r"((r)[14]), "=r"((r)[15]), \
          "=r"((r)[16]), "=r"((r)[17]), "=r"((r)[18]), "=r"((r)[19]), \
          "=r"((r)[20]), "=r"((r)[21]), "=r"((r)[22]), "=r"((r)[23]), \
          "=r"((r)[24]), "=r"((r)[25]), "=r"((r)[26]), "=r"((r)[27]), \
          "=r"((r)[28]), "=r"((r)[29]), "=r"((r)[30]), "=r"((r)[31]) \
        : "r"(tmem_addr))
#endif  // tcgen05 path helpers

// ---------------------------------------------------------------------------
// Main GEMM: out[M,N] = Xh@W + Xl@W + bias, fp32 accumulate
// ---------------------------------------------------------------------------
__global__ void __launch_bounds__(NTHREADS, 1)
w2a16_gemm_kernel(const float* __restrict__ bias, float* __restrict__ out) {
    extern __shared__ char smem_raw[];
    uint32_t sb0 = smem_u32(smem_raw);
    uint32_t sb = (sb0 + 1023) & ~1023u;
    const uint32_t stage0 = sb + 1024;

    const int tid = threadIdx.x;
    const int wid = tid >> 5;
    const int lid = tid & 31;

    // Supertile raster (8 M-tiles per N column) for L2 reuse
    const int bid = blockIdx.x;
    const int rem = bid % (8 * TILES_N);
    const int m0 = ((bid / (8 * TILES_N)) * 8 + (rem & 7)) * TM;
    const int n0 = (rem >> 3) * TN;

#if defined(__CUDA_ARCH__) && defined(__CUDA_ARCH_FEAT_SM103_ALL)
    // =======================================================================
    // tcgen05 path
    // =======================================================================
    const uint32_t fullb  = sb + 16;
    const uint32_t emptyb = sb + 40;
    const uint32_t doneb  = sb + 64;

    if (tid == 0) {
#pragma unroll
        for (int s = 0; s < STAGES; ++s) {
            mbar_init(fullb + 8 * s, NTHREADS);
            mbar_init(emptyb + 8 * s, 1);
        }
        mbar_init(doneb, 1);
    }
    if (wid == 0) {
        TCGEN05_ALLOC(sb, 256);
        TCGEN05_RELINQUISH();
    }
    __syncthreads();

    uint32_t tmem;
    asm volatile("ld.shared.b32 %0, [%1];" : "=r"(tmem) : "r"(sb));

    unsigned pph = (1u << STAGES) - 1;
    unsigned cph = 0;

#pragma unroll
    for (int s = 0; s < STAGES; ++s) {
        mbar_wait(emptyb + 8 * s, (pph >> s) & 1);
        pph ^= 1u << s;
        fill_stage(s, stage0 + s * STAGE_BYTES, m0, n0, tid);
        cp_async_arrive(fullb + 8 * s);
    }

    for (int k = 0; k < KITERS; ++k) {
        const int s = k % STAGES;
        const uint32_t stage_sm = stage0 + s * STAGE_BYTES;

        if (tid == 0) {
            mbar_wait(fullb + 8 * s, (cph >> s) & 1);
            cph ^= 1u << s;
            fence_proxy_async_shared();
            uint64_t da0 = make_desc(stage_sm);
            uint64_t da1 = make_desc(stage_sm + 16384);
            uint64_t db0 = make_desc(stage_sm + 32768);
            uint64_t db1 = make_desc(stage_sm + 49152);
#pragma unroll
            for (int pl = 0; pl < 2; ++pl) {
                uint64_t da = pl ? da1 : da0;
#pragma unroll
                for (int ks = 0; ks < 4; ++ks) {
                    uint32_t acc = ((k | pl | ks) != 0) ? 1u : 0u;
                    mma_f16_ss(tmem,       da + 2 * ks, db0 + 2 * ks, acc);
                    mma_f16_ss(tmem + 128, da + 2 * ks, db1 + 2 * ks, acc);
                }
            }
            tcgen05_commit((k == KITERS - 1) ? doneb : (emptyb + 8 * s));
        }

        const int nk = k + STAGES;
        if (nk < KITERS) {
            mbar_wait(emptyb + 8 * s, (pph >> s) & 1);
            pph ^= 1u << s;
            fill_stage(nk, stage_sm, m0, n0, tid);
            cp_async_arrive(fullb + 8 * s);
        }
    }

    mbar_wait(doneb, 0);
    TCGEN05_FENCE_AFTER();

    const int sub = wid & 3;
    const int quarter = wid >> 2;
    const int m = m0 + sub * 32 + lid;
#pragma unroll
    for (int ch = 0; ch < 2; ++ch) {
        const int cbase = quarter * 64 + ch * 32;
        uint32_t r[32];
        TCGEN05_LD_32X32B_X32(r, tmem + cbase);
        TCGEN05_WAIT_LD();
        const int n = n0 + cbase;
        float4* o = reinterpret_cast<float4*>(out + (size_t)m * NDIM + n);
        const float4* bz = reinterpret_cast<const float4*>(bias + n);
#pragma unroll
        for (int q4 = 0; q4 < 8; ++q4) {
            float4 b4 = bz[q4];
            float4 v;
            v.x = __uint_as_float(r[4 * q4 + 0]) + b4.x;
            v.y = __uint_as_float(r[4 * q4 + 1]) + b4.y;
            v.z = __uint_as_float(r[4 * q4 + 2]) + b4.z;
            v.w = __uint_as_float(r[4 * q4 + 3]) + b4.w;
            o[q4] = v;
        }
    }
    TCGEN05_FENCE_BEFORE();
    __syncthreads();
    if (wid == 0) TCGEN05_DEALLOC(tmem, 256);

#else
    // =======================================================================
    // Fallback: mma.sync.m16n8k16 (compute_103-safe), 16 warps 4m x 4n,
    // warp tile 32x64, B fragments reused across both A planes.
    // =======================================================================
    const int warp_m = wid & 3;        // 0..3  -> m offset 32*warp_m
    const int warp_n = wid >> 2;       // 0..3  -> n offset 64*warp_n

    float acc[2][8][4];
#pragma unroll
    for (int i = 0; i < 2; ++i)
#pragma unroll
        for (int j = 0; j < 8; ++j)
#pragma unroll
            for (int c = 0; c < 4; ++c) acc[i][j][c] = 0.f;

    // Prologue fills
#pragma unroll
    for (int s = 0; s < STAGES; ++s) {
        fill_stage(s, stage0 + s * STAGE_BYTES, m0, n0, tid);
        cp_commit();
    }

    // Per-lane ldmatrix row-byte components (row * 128B)
    const uint32_t rbA = (uint32_t)(warp_m * 32 + (lid & 15)) * 128;
    const uint32_t colA = (uint32_t)((lid >> 4) * 16);        // +8 halves
    const uint32_t rbB = (uint32_t)(warp_n * 64 + ((lid >> 4) & 1) * 8 + (lid & 7)) * 128;
    const uint32_t colB = (uint32_t)(((lid >> 3) & 1) * 16);  // +8 halves

    for (int k = 0; k < KITERS; ++k) {
        const int s = k % STAGES;
        const uint32_t stage_sm = stage0 + s * STAGE_BYTES;

        cp_wait2();
        __syncthreads();

#pragma unroll
        for (int ks = 0; ks < 4; ++ks) {
            const uint32_t kb = (uint32_t)ks * 32;   // ks*16 halves

            // B fragments: 4 x4-ldmatrix -> 8 n-tiles
            uint32_t b0[4], b1[4], b2[4], b3[4];
            uint32_t* bt[4] = {b0, b1, b2, b3};
#pragma unroll
            for (int t = 0; t < 4; ++t) {
                uint32_t raw = rbB + (uint32_t)t * 2048 + kb + colB;
                uint32_t addr = stage_sm + 32768 + (raw ^ ((raw >> 3) & 0x70));
                asm volatile(
                    "ldmatrix.sync.aligned.m8n8.x4.shared.b16 {%0,%1,%2,%3}, [%4];"
                    : "=r"(bt[t][0]), "=r"(bt[t][1]), "=r"(bt[t][2]), "=r"(bt[t][3])
                    : "r"(addr));
            }

#pragma unroll
            for (int pl = 0; pl < 2; ++pl) {
                const uint32_t plane_off = pl ? 16384u : 0u;
                uint32_t a[2][4];
#pragma unroll
                for (int mt = 0; mt < 2; ++mt) {
                    uint32_t raw = rbA + (uint32_t)mt * 2048 + kb + colA;
                    uint32_t addr = stage_sm + plane_off + (raw ^ ((raw >> 3) & 0x70));
                    asm volatile(
                        "ldmatrix.sync.aligned.m8n8.x4.shared.b16 {%0,%1,%2,%3}, [%4];"
                        : "=r"(a[mt][0]), "=r"(a[mt][1]), "=r"(a[mt][2]), "=r"(a[mt][3])
                        : "r"(addr));
                }
#pragma unroll
                for (int mt = 0; mt < 2; ++mt) {
#pragma unroll
                    for (int t = 0; t < 4; ++t) {
#pragma unroll
                        for (int half = 0; half < 2; ++half) {
                            const int ni = t * 2 + half;
                            float* c = acc[mt][ni];
                            uint32_t bb0 = bt[t][half * 2];
                            uint32_t bb1 = bt[t][half * 2 + 1];
                            asm volatile(
                                "mma.sync.aligned.m16n8k16.row.col.f32.f16.f16.f32 "
                                "{%0,%1,%2,%3}, {%4,%5,%6,%7}, {%8,%9}, {%0,%1,%2,%3};"
                                : "+f"(c[0]), "+f"(c[1]), "+f"(c[2]), "+f"(c[3])
                                : "r"(a[mt][0]), "r"(a[mt][1]), "r"(a[mt][2]), "r"(a[mt][3]),
                                  "r"(bb0), "r"(bb1));
                        }
                    }
                }
            }
        }

        __syncthreads();
        const int nk = k + STAGES;
        if (nk < KITERS)
            fill_stage(nk, stage0 + s * STAGE_BYTES, m0, n0, tid);
        cp_commit();   // one group per iteration (possibly empty) keeps wait_group math exact
    }

    // Epilogue: out = acc + bias
    const int mrow0 = m0 + warp_m * 32 + (lid >> 2);
    const int ncol0 = n0 + warp_n * 64 + (lid & 3) * 2;
#pragma unroll
    for (int mt = 0; mt < 2; ++mt) {
#pragma unroll
        for (int ni = 0; ni < 8; ++ni) {
            const int n = ncol0 + ni * 8;
            const float bx = bias[n];
            const float by = bias[n + 1];
            const int mA = mrow0 + mt * 16;
            float2 v0 = {acc[mt][ni][0] + bx, acc[mt][ni][1] + by};
            float2 v1 = {acc[mt][ni][2] + bx, acc[mt][ni][3] + by};
            *reinterpret_cast<float2*>(out + (size_t)mA * NDIM + n) = v0;
            *reinterpret_cast<float2*>(out + (size_t)(mA + 8) * NDIM + n) = v1;
        }
    }
#endif
}

// ---------------------------------------------------------------------------
// Launch
// ---------------------------------------------------------------------------
extern "C" void kernel_launch(void* const* d_in, const int* in_sizes, int n_in,
                              void* d_out, int out_size) {
    (void)in_sizes; (void)n_in; (void)out_size;
    const float* input   = (const float*)d_in[0];
    const int*   qweight = (const int*)d_in[1];
    const float* scale   = (const float*)d_in[2];
    const float* zp      = (const float*)d_in[3];
    const float* bias    = (const float*)d_in[4];
    float* out = (float*)d_out;

    cudaFuncSetAttribute(w2a16_gemm_kernel,
                         cudaFuncAttributeMaxDynamicSharedMemorySize, SMEM_TOTAL);

    split_x_kernel<<<(MDIM * (size_t)KDIM / 4) / 256, 256>>>(
        reinterpret_cast<const float4*>(input));
    dequant_kernel<<<dim3(NDIM / 32, KDIM / 32), dim3(32, 8)>>>(qweight, scale, zp);
    w2a16_gemm_kernel<<<TILES_M * TILES_N, NTHREADS, SMEM_TOTAL>>>(bias, out);
}